// round 13
// baseline (speedup 1.0000x reference)
#include <cuda_runtime.h>
#include <cuda_bf16.h>
#include <math.h>

#define H 512
#define W 512
#define WPR 16                 // 32-bit words per row
#define GRID 256               // 2 rows per block, fully self-contained
#define MISS (1 << 20)

// Scratch (allocation-free rule: __device__ globals)
__device__ float d_blkNum[GRID];
__device__ float d_blkDen[GRID];
__device__ unsigned d_cnt;     // zero-init; atomicInc wraps -> self-resetting

// ---------------------------------------------------------------------------
// Cold path: recompute raw/surface mask words directly from float inputs.
// Only used for pixels with nearest surface distance^2 > 10 (P ~ 3e-5 / run).
// ---------------------------------------------------------------------------
__device__ __noinline__ unsigned raw_word_f(const float* __restrict__ src,
                                            int r, int w) {
    if (r < 0 || r >= H) return 0u;
    const float* p = src + r * W + w * 32;
    unsigned x = 0;
    for (int j = 0; j < 32; ++j)
        if (p[j] != 0.0f) x |= 1u << j;
    return x;
}

__device__ __noinline__ unsigned sur_word_f(const float* __restrict__ src,
                                            int r, int w) {
    if (r < 0 || r >= H || w < 0 || w >= WPR) return 0u;
    unsigned cen = raw_word_f(src, r, w);
    unsigned up  = raw_word_f(src, r - 1, w);
    unsigned dn  = raw_word_f(src, r + 1, w);
    unsigned lb  = (w > 0)  ? ((raw_word_f(src, r, w - 1) >> 31) & 1u) : 0u;
    unsigned rb  = (w < 15) ? (raw_word_f(src, r, w + 1) & 1u) : 0u;
    unsigned lm = (cen << 1) | lb;
    unsigned rm = (cen >> 1) | (rb << 31);
    return cen & ~(up & dn & lm & rm);
}

__device__ __noinline__ float search_fb(const float* __restrict__ src,
                                        int r, int w, int bit) {
    float best = 1e12f;
    for (int dr = 0; dr < H; ++dr) {
        int dr2 = dr * dr;
        if ((float)dr2 >= best) break;
        for (int sgn = 0; sgn < 2; ++sgn) {
            if (sgn == 1 && dr == 0) continue;
            int gr = sgn ? (r + dr) : (r - dr);
            if (gr < 0 || gr >= H) continue;
            unsigned lo = sur_word_f(src, gr, w - 1);
            unsigned mi = sur_word_f(src, gr, w);
            unsigned hi = sur_word_f(src, gr, w + 1);
            unsigned long long up =
                (((unsigned long long)(mi & (0xFFFFFFFFu >> (31 - bit)))) << 32) |
                (unsigned long long)lo;
            unsigned long long dn =
                (((unsigned long long)hi) << (32 - bit)) |
                (unsigned long long)(mi >> bit);
            int dl = up ? (bit + 32) - (63 - __clzll(up)) : MISS;
            int drr = dn ? (__ffsll((long long)dn) - 1)   : MISS;
            int dc = min(dl, drr);
            if (dc <= 32) {
                best = fminf(best, (float)(dr2 + dc * dc));
            } else if ((float)(dr2 + 1024) < best) {
                int dfl = MISS, dfr = MISS;
                for (int ww = w - 2; ww >= 0; --ww) {
                    unsigned x = sur_word_f(src, gr, ww);
                    if (x) { dfl = (w - ww) * 32 + bit - (31 - __clz(x)); break; }
                }
                for (int ww = w + 2; ww < WPR; ++ww) {
                    unsigned x = sur_word_f(src, gr, ww);
                    if (x) { dfr = (ww - w) * 32 - bit + (__ffs(x) - 1); break; }
                }
                int dm = min(min(dfl, dfr), dc);
                if (dm < MISS)
                    best = fminf(best, (float)(dr2 + dm * dm));
            }
        }
    }
    return sqrtf(best);
}

// ===========================================================================
// Single kernel, no grid barrier, ONE staging sync on the main path.
// Block b handles rows 2b, 2b+1:
//   float4 loads -> nibble pack -> shuffle-OR into raw words (shared)
//   -> sync -> counting threads erode on the fly (sliding window) and do
//   ball-dilation counting -> deterministic fold via last-block pattern.
// ===========================================================================
__global__ void __launch_bounds__(512, 2) k_all(const float* __restrict__ pred,
                                                const float* __restrict__ gt,
                                                float* __restrict__ out) {
    __shared__ unsigned sraw[2][10][WPR];   // raw rows gb-4..gb+5
    __shared__ float wNum[16], wDen[16];
    __shared__ bool  isLast;

    const int c = threadIdx.x;
    const int lane = c & 31;
    const int wwarp = c >> 5;
    const int gb = blockIdx.x * 2;

    // ---- float4 binarize + pack: warp covers 128 cols of one row/round ----
    // warp w: row offset (w>>2) within round, col chunk 128*(w&3).
    {
        const int rowoff = wwarp >> 2;                // 0..3
        const int colbase = (wwarp & 3) * 128 + lane * 4;
        const int shift = (lane & 7) * 4;
        const int wordidx = (wwarp & 3) * 4 + (lane >> 3);

        #pragma unroll
        for (int feat = 0; feat < 2; ++feat) {
            const float* src = feat ? gt : pred;
            #pragma unroll
            for (int j = 0; j < 3; ++j) {
                int rr = 4 * j + rowoff;             // 0..11 (warp-uniform)
                if (rr >= 10) continue;
                int gr = gb - 4 + rr;                // warp-uniform
                unsigned nib = 0;
                if (gr >= 0 && gr < H) {
                    float4 v = *(const float4*)(src + gr * W + colbase);
                    nib = (v.x != 0.0f ? 1u : 0u) | (v.y != 0.0f ? 2u : 0u) |
                          (v.z != 0.0f ? 4u : 0u) | (v.w != 0.0f ? 8u : 0u);
                }
                unsigned x = nib << shift;
                x |= __shfl_xor_sync(0xFFFFFFFFu, x, 1);
                x |= __shfl_xor_sync(0xFFFFFFFFu, x, 2);
                x |= __shfl_xor_sync(0xFFFFFFFFu, x, 4);
                if ((lane & 7) == 0) sraw[feat][rr][wordidx] = x;
            }
        }
    }
    __syncthreads();

    // ---- counting with on-the-fly erosion (64 active threads) ----
    float num = 0.0f;
    float den = 0.0f;

    if (c < 64) {
        const int f = c >> 5;            // dilated (source) feature
        const int rloc = (c >> 4) & 1;   // 0..1
        const int w = c & 15;
        const int gr = gb + rloc;

        // lds with word-bound zero padding (row index always in range)
        #define LDSW(ff, ri, ww) \
            (((ww) >= 0 && (ww) < WPR) ? sraw[ff][ri][ww] : 0u)

        // target word: surface of feature f^1 at raw row rloc+4, word w
        unsigned tgt;
        {
            unsigned cen = LDSW(f ^ 1, rloc + 4, w);
            unsigned up  = LDSW(f ^ 1, rloc + 3, w);
            unsigned dn  = LDSW(f ^ 1, rloc + 5, w);
            unsigned lw  = LDSW(f ^ 1, rloc + 4, w - 1);
            unsigned rw  = LDSW(f ^ 1, rloc + 4, w + 1);
            tgt = cen & ~(up & dn & ((cen << 1) | (lw >> 31))
                                   & ((cen >> 1) | (rw << 31)));
        }
        den = (float)__popc(tgt);

        // sliding 3x5 raw window for source-surface rows rloc+3+dr (dr=-3..3)
        unsigned rm1[5], r0[5], rp1[5];
        #pragma unroll
        for (int k = 0; k < 5; ++k) {
            int ww = w - 2 + k;
            rm1[k] = LDSW(f, rloc + 0, ww);
            r0[k]  = LDSW(f, rloc + 1, ww);
            rp1[k] = LDSW(f, rloc + 2, ww);
        }

        unsigned a0c0 = 0, a0c1 = 0, a0c2 = 0, a0c3 = 0;
        unsigned a1c0 = 0, a1c1 = 0, a1c2 = 0, a1c3 = 0;
        unsigned a2c0 = 0, a2c1 = 0, a2c2 = 0;
        unsigned a3c0 = 0, a3c1 = 0;

        #pragma unroll
        for (int dr = -3; dr <= 3; ++dr) {
            unsigned s[3];
            #pragma unroll
            for (int k = 1; k <= 3; ++k) {
                unsigned cen = r0[k];
                unsigned lm = (cen << 1) | (r0[k - 1] >> 31);
                unsigned rm = (cen >> 1) | (r0[k + 1] << 31);
                s[k - 1] = cen & ~(rm1[k] & rp1[k] & lm & rm);
            }
            unsigned lo = s[0], mi = s[1], hi = s[2];
            unsigned c0 = mi;
            unsigned c1 = __funnelshift_r(mi, hi, 1) | __funnelshift_l(lo, mi, 1);
            const int adr = (dr < 0) ? -dr : dr;
            if (adr == 0) {
                a0c0 = c0; a0c1 = c1;
                a0c2 = __funnelshift_r(mi, hi, 2) | __funnelshift_l(lo, mi, 2);
                a0c3 = __funnelshift_r(mi, hi, 3) | __funnelshift_l(lo, mi, 3);
            } else if (adr == 1) {
                a1c0 |= c0; a1c1 |= c1;
                a1c2 |= __funnelshift_r(mi, hi, 2) | __funnelshift_l(lo, mi, 2);
                a1c3 |= __funnelshift_r(mi, hi, 3) | __funnelshift_l(lo, mi, 3);
            } else if (adr == 2) {
                a2c0 |= c0; a2c1 |= c1;
                a2c2 |= __funnelshift_r(mi, hi, 2) | __funnelshift_l(lo, mi, 2);
            } else {
                a3c0 |= c0; a3c1 |= c1;
            }
            if (dr < 3) {
                #pragma unroll
                for (int k = 0; k < 5; ++k) {
                    rm1[k] = r0[k];
                    r0[k]  = rp1[k];
                    rp1[k] = LDSW(f, rloc + 6 + dr, w - 2 + k);
                }
            }
        }
        #undef LDSW

        // incremental ball dilations: d^2 = 0,1,2,4,5,8,9,10
        unsigned D = a0c0, Dn;
        Dn = D | a0c1 | a1c0; num += 1.0f        * (float)__popc(tgt & Dn & ~D); D = Dn;
        Dn = D | a1c1;        num += 1.41421356f * (float)__popc(tgt & Dn & ~D); D = Dn;
        Dn = D | a0c2 | a2c0; num += 2.0f        * (float)__popc(tgt & Dn & ~D); D = Dn;
        Dn = D | a1c2 | a2c1; num += 2.23606798f * (float)__popc(tgt & Dn & ~D); D = Dn;
        Dn = D | a2c2;        num += 2.82842712f * (float)__popc(tgt & Dn & ~D); D = Dn;
        Dn = D | a0c3 | a3c0; num += 3.0f        * (float)__popc(tgt & Dn & ~D); D = Dn;
        Dn = D | a1c3 | a3c1; num += 3.16227766f * (float)__popc(tgt & Dn & ~D); D = Dn;

        // cold exact fallback (recomputes masks straight from float inputs)
        unsigned rem = tgt & ~D;
        while (rem) {
            int bt = __ffs(rem) - 1;
            rem &= rem - 1u;
            num += search_fb(f ? gt : pred, gr, w, bt);
        }
    }

    // ---- deterministic reduction + last-block fold ----
    #pragma unroll
    for (int off = 16; off > 0; off >>= 1) {
        num += __shfl_down_sync(0xFFFFFFFFu, num, off);
        den += __shfl_down_sync(0xFFFFFFFFu, den, off);
    }
    if (lane == 0) { wNum[wwarp] = num; wDen[wwarp] = den; }
    __syncthreads();

    if (wwarp == 0) {
        float n = (lane < 16) ? wNum[lane] : 0.0f;
        float d = (lane < 16) ? wDen[lane] : 0.0f;
        #pragma unroll
        for (int off = 8; off > 0; off >>= 1) {
            n += __shfl_down_sync(0xFFFFFFFFu, n, off);
            d += __shfl_down_sync(0xFFFFFFFFu, d, off);
        }
        if (lane == 0) {
            d_blkNum[blockIdx.x] = n;
            d_blkDen[blockIdx.x] = d;
            __threadfence();
            unsigned old = atomicInc(&d_cnt, GRID - 1);  // wraps -> self-reset
            isLast = (old == GRID - 1);
        }
    }
    __syncthreads();

    if (isLast) {
        float n = (c < GRID) ? d_blkNum[c] : 0.0f;
        float d = (c < GRID) ? d_blkDen[c] : 0.0f;
        #pragma unroll
        for (int off = 16; off > 0; off >>= 1) {
            n += __shfl_down_sync(0xFFFFFFFFu, n, off);
            d += __shfl_down_sync(0xFFFFFFFFu, d, off);
        }
        if (lane == 0) { wNum[wwarp] = n; wDen[wwarp] = d; }
        __syncthreads();
        if (wwarp == 0) {
            float nn = (lane < 16) ? wNum[lane] : 0.0f;
            float dd = (lane < 16) ? wDen[lane] : 0.0f;
            #pragma unroll
            for (int off = 8; off > 0; off >>= 1) {
                nn += __shfl_down_sync(0xFFFFFFFFu, nn, off);
                dd += __shfl_down_sync(0xFFFFFFFFu, dd, off);
            }
            if (lane == 0) out[0] = nn / dd;
        }
    }
}

extern "C" void kernel_launch(void* const* d_in, const int* in_sizes, int n_in,
                              void* d_out, int out_size) {
    const float* pred = (const float*)d_in[0];
    const float* gt   = (const float*)d_in[1];
    float* out = (float*)d_out;

    k_all<<<GRID, 512>>>(pred, gt, out);
}

// round 14
// speedup vs baseline: 1.0929x; 1.0929x over previous
#include <cuda_runtime.h>
#include <cuda_bf16.h>
#include <math.h>

#define H 512
#define W 512
#define WPR 16                 // 32-bit words per row
#define GRID 256               // 2 rows per block, fully self-contained
#define MISS (1 << 20)

// Scratch (allocation-free rule: __device__ globals)
__device__ float d_num;        // global scalar accumulators (reset by last block)
__device__ float d_den;
__device__ unsigned d_cnt;     // zero-init; atomicInc wraps -> self-resetting

// ---------------------------------------------------------------------------
// Cold path: recompute raw/surface mask words directly from float inputs.
// Only used for pixels with nearest surface distance^2 > 10 (P ~ 3e-5 / run).
// ---------------------------------------------------------------------------
__device__ __noinline__ unsigned raw_word_f(const float* __restrict__ src,
                                            int r, int w) {
    if (r < 0 || r >= H) return 0u;
    const float* p = src + r * W + w * 32;
    unsigned x = 0;
    for (int j = 0; j < 32; ++j)
        if (p[j] != 0.0f) x |= 1u << j;
    return x;
}

__device__ __noinline__ unsigned sur_word_f(const float* __restrict__ src,
                                            int r, int w) {
    if (r < 0 || r >= H || w < 0 || w >= WPR) return 0u;
    unsigned cen = raw_word_f(src, r, w);
    unsigned up  = raw_word_f(src, r - 1, w);
    unsigned dn  = raw_word_f(src, r + 1, w);
    unsigned lb  = (w > 0)  ? ((raw_word_f(src, r, w - 1) >> 31) & 1u) : 0u;
    unsigned rb  = (w < 15) ? (raw_word_f(src, r, w + 1) & 1u) : 0u;
    unsigned lm = (cen << 1) | lb;
    unsigned rm = (cen >> 1) | (rb << 31);
    return cen & ~(up & dn & lm & rm);
}

__device__ __noinline__ float search_fb(const float* __restrict__ src,
                                        int r, int w, int bit) {
    float best = 1e12f;
    for (int dr = 0; dr < H; ++dr) {
        int dr2 = dr * dr;
        if ((float)dr2 >= best) break;
        for (int sgn = 0; sgn < 2; ++sgn) {
            if (sgn == 1 && dr == 0) continue;
            int gr = sgn ? (r + dr) : (r - dr);
            if (gr < 0 || gr >= H) continue;
            unsigned lo = sur_word_f(src, gr, w - 1);
            unsigned mi = sur_word_f(src, gr, w);
            unsigned hi = sur_word_f(src, gr, w + 1);
            unsigned long long up =
                (((unsigned long long)(mi & (0xFFFFFFFFu >> (31 - bit)))) << 32) |
                (unsigned long long)lo;
            unsigned long long dn =
                (((unsigned long long)hi) << (32 - bit)) |
                (unsigned long long)(mi >> bit);
            int dl = up ? (bit + 32) - (63 - __clzll(up)) : MISS;
            int drr = dn ? (__ffsll((long long)dn) - 1)   : MISS;
            int dc = min(dl, drr);
            if (dc <= 32) {
                best = fminf(best, (float)(dr2 + dc * dc));
            } else if ((float)(dr2 + 1024) < best) {
                int dfl = MISS, dfr = MISS;
                for (int ww = w - 2; ww >= 0; --ww) {
                    unsigned x = sur_word_f(src, gr, ww);
                    if (x) { dfl = (w - ww) * 32 + bit - (31 - __clz(x)); break; }
                }
                for (int ww = w + 2; ww < WPR; ++ww) {
                    unsigned x = sur_word_f(src, gr, ww);
                    if (x) { dfr = (ww - w) * 32 - bit + (__ffs(x) - 1); break; }
                }
                int dm = min(min(dfl, dfr), dc);
                if (dm < MISS)
                    best = fminf(best, (float)(dr2 + dm * dm));
            }
        }
    }
    return sqrtf(best);
}

// ===========================================================================
// Single kernel (R12 base). Block b handles rows 2b, 2b+1:
//   scalar loads + ballot pack -> erosion stage -> ball-dilation counting.
// NEW tail: per-warp fold only (warps 0,1), direct scalar atomicAdds, last
// arriving block divides and resets. No per-block partial arrays, no fold.
// ===========================================================================
__global__ void __launch_bounds__(512, 2) k_all(const float* __restrict__ pred,
                                                const float* __restrict__ gt,
                                                float* __restrict__ out) {
    __shared__ unsigned sraw[2][10][WPR];   // raw rows gb-4..gb+5
    __shared__ unsigned stg[2][8][18];      // surface rows gb-3..gb+4, padded
    __shared__ unsigned sdone;

    const int c = threadIdx.x;
    const int lane = c & 31;
    const int wwarp = c >> 5;               // warp id == word index
    const int gb = blockIdx.x * 2;

    if (c == 0) sdone = 0u;

    // ---- load 10 rows of both features (20 independent coalesced LDGs) ----
    float pv[10], gv[10];
    #pragma unroll
    for (int rr = 0; rr < 10; ++rr) {
        int gr = gb - 4 + rr;
        bool ok = (gr >= 0) && (gr < H);
        pv[rr] = ok ? pred[gr * W + c] : 0.0f;
        gv[rr] = ok ? gt[gr * W + c]   : 0.0f;
    }
    #pragma unroll
    for (int rr = 0; rr < 10; ++rr) {
        unsigned ba = __ballot_sync(0xFFFFFFFFu, pv[rr] != 0.0f);
        unsigned bb = __ballot_sync(0xFFFFFFFFu, gv[rr] != 0.0f);
        if (lane == 0) { sraw[0][rr][wwarp] = ba; sraw[1][rr][wwarp] = bb; }
    }
    __syncthreads();

    // ---- bitwise erosion -> padded surface rows (8 rows x 16 words x 2) ----
    if (c < 256) {
        int f = c >> 7, rest = c & 127;
        int rr = rest >> 4, ww = rest & 15;   // rr 0..7 -> surface row gb-3+rr
        int ri = rr + 1;                      // center raw row index
        unsigned cen = sraw[f][ri][ww];
        unsigned up = sraw[f][ri - 1][ww];
        unsigned dn = sraw[f][ri + 1][ww];
        unsigned lw = (ww > 0)  ? sraw[f][ri][ww - 1] : 0u;
        unsigned rw = (ww < 15) ? sraw[f][ri][ww + 1] : 0u;
        unsigned lm = (cen << 1) | (lw >> 31);
        unsigned rm = (cen >> 1) | (rw << 31);
        stg[f][rr][ww + 1] = cen & ~(up & dn & lm & rm);
    } else if (c < 288) {
        int idx = c - 256;                    // 32 pad words -> 0
        int f = idx >> 4, rest = idx & 15;
        stg[f][rest >> 1][(rest & 1) ? 17 : 0] = 0u;
    }
    __syncthreads();

    // warps 2..15 are done (exited threads skip remaining code)
    if (wwarp >= 2) return;

    // ---- per-word ball-dilation counting (warps 0,1 = 64 threads) ----
    float num = 0.0f;
    float den = 0.0f;

    {
        const int f = c >> 5;            // dilated (source) feature
        const int rloc = (c >> 4) & 1;   // 0..1
        const int w = c & 15;
        const int gr = gb + rloc;

        unsigned a0c0, a0c1, a0c2, a0c3;
        unsigned a1c0 = 0, a1c1 = 0, a1c2 = 0, a1c3 = 0;
        unsigned a2c0 = 0, a2c1 = 0, a2c2 = 0;
        unsigned a3c0 = 0, a3c1 = 0;

        #pragma unroll
        for (int dr = -3; dr <= 3; ++dr) {
            const unsigned* row = &stg[f][rloc + 3 + dr][0];
            unsigned lo = row[w], mi = row[w + 1], hi = row[w + 2];
            unsigned c0 = mi;
            unsigned c1 = __funnelshift_r(mi, hi, 1) | __funnelshift_l(lo, mi, 1);
            const int adr = (dr < 0) ? -dr : dr;
            if (adr == 0) {
                a0c0 = c0; a0c1 = c1;
                a0c2 = __funnelshift_r(mi, hi, 2) | __funnelshift_l(lo, mi, 2);
                a0c3 = __funnelshift_r(mi, hi, 3) | __funnelshift_l(lo, mi, 3);
            } else if (adr == 1) {
                a1c0 |= c0; a1c1 |= c1;
                a1c2 |= __funnelshift_r(mi, hi, 2) | __funnelshift_l(lo, mi, 2);
                a1c3 |= __funnelshift_r(mi, hi, 3) | __funnelshift_l(lo, mi, 3);
            } else if (adr == 2) {
                a2c0 |= c0; a2c1 |= c1;
                a2c2 |= __funnelshift_r(mi, hi, 2) | __funnelshift_l(lo, mi, 2);
            } else {
                a3c0 |= c0; a3c1 |= c1;
            }
        }

        const unsigned tgt = stg[f ^ 1][rloc + 3][w + 1];
        den = (float)__popc(tgt);

        // incremental ball dilations: d^2 = 0,1,2,4,5,8,9,10
        unsigned D = a0c0, Dn;
        Dn = D | a0c1 | a1c0; num += 1.0f        * (float)__popc(tgt & Dn & ~D); D = Dn;
        Dn = D | a1c1;        num += 1.41421356f * (float)__popc(tgt & Dn & ~D); D = Dn;
        Dn = D | a0c2 | a2c0; num += 2.0f        * (float)__popc(tgt & Dn & ~D); D = Dn;
        Dn = D | a1c2 | a2c1; num += 2.23606798f * (float)__popc(tgt & Dn & ~D); D = Dn;
        Dn = D | a2c2;        num += 2.82842712f * (float)__popc(tgt & Dn & ~D); D = Dn;
        Dn = D | a0c3 | a3c0; num += 3.0f        * (float)__popc(tgt & Dn & ~D); D = Dn;
        Dn = D | a1c3 | a3c1; num += 3.16227766f * (float)__popc(tgt & Dn & ~D); D = Dn;

        // cold exact fallback (recomputes masks straight from float inputs)
        unsigned rem = tgt & ~D;
        while (rem) {
            int bt = __ffs(rem) - 1;
            rem &= rem - 1u;
            num += search_fb(f ? gt : pred, gr, w, bt);
        }
    }

    // ---- per-warp fold + direct scalar atomics ----
    #pragma unroll
    for (int off = 16; off > 0; off >>= 1) {
        num += __shfl_down_sync(0xFFFFFFFFu, num, off);
        den += __shfl_down_sync(0xFFFFFFFFu, den, off);
    }

    if (lane == 0) {
        atomicAdd(&d_num, num);
        atomicAdd(&d_den, den);
        __threadfence();
        // second of this block's two warps signals block completion
        unsigned prev = atomicAdd(&sdone, 1u);
        if (prev == 1u) {
            unsigned old = atomicInc(&d_cnt, GRID - 1);  // wraps -> self-reset
            if (old == GRID - 1) {
                __threadfence();
                float nn = atomicAdd(&d_num, 0.0f);
                float dd = atomicAdd(&d_den, 0.0f);
                out[0] = nn / dd;
                d_num = 0.0f;     // reset for next graph replay
                d_den = 0.0f;
            }
        }
    }
}

extern "C" void kernel_launch(void* const* d_in, const int* in_sizes, int n_in,
                              void* d_out, int out_size) {
    const float* pred = (const float*)d_in[0];
    const float* gt   = (const float*)d_in[1];
    float* out = (float*)d_out;

    k_all<<<GRID, 512>>>(pred, gt, out);
}

// round 15
// speedup vs baseline: 1.1679x; 1.0687x over previous
#include <cuda_runtime.h>
#include <cuda_bf16.h>
#include <math.h>

#define H 512
#define W 512
#define WPR 16                 // 32-bit words per row
#define GRID 128               // 4 rows per block, oe=1 (one wave, 1 block/SM)
#define MISS (1 << 20)

// Scratch (allocation-free rule: __device__ globals)
__device__ float d_blkNum[GRID];
__device__ float d_blkDen[GRID];
__device__ unsigned d_cnt;     // zero-init; atomicInc wraps -> self-resetting

// ---------------------------------------------------------------------------
// Cold path: recompute raw/surface mask words directly from float inputs.
// Only used for pixels with nearest surface distance^2 > 10 (P ~ 3e-5 / run).
// ---------------------------------------------------------------------------
__device__ __noinline__ unsigned raw_word_f(const float* __restrict__ src,
                                            int r, int w) {
    if (r < 0 || r >= H) return 0u;
    const float* p = src + r * W + w * 32;
    unsigned x = 0;
    for (int j = 0; j < 32; ++j)
        if (p[j] != 0.0f) x |= 1u << j;
    return x;
}

__device__ __noinline__ unsigned sur_word_f(const float* __restrict__ src,
                                            int r, int w) {
    if (r < 0 || r >= H || w < 0 || w >= WPR) return 0u;
    unsigned cen = raw_word_f(src, r, w);
    unsigned up  = raw_word_f(src, r - 1, w);
    unsigned dn  = raw_word_f(src, r + 1, w);
    unsigned lb  = (w > 0)  ? ((raw_word_f(src, r, w - 1) >> 31) & 1u) : 0u;
    unsigned rb  = (w < 15) ? (raw_word_f(src, r, w + 1) & 1u) : 0u;
    unsigned lm = (cen << 1) | lb;
    unsigned rm = (cen >> 1) | (rb << 31);
    return cen & ~(up & dn & lm & rm);
}

__device__ __noinline__ float search_fb(const float* __restrict__ src,
                                        int r, int w, int bit) {
    float best = 1e12f;
    for (int dr = 0; dr < H; ++dr) {
        int dr2 = dr * dr;
        if ((float)dr2 >= best) break;
        for (int sgn = 0; sgn < 2; ++sgn) {
            if (sgn == 1 && dr == 0) continue;
            int gr = sgn ? (r + dr) : (r - dr);
            if (gr < 0 || gr >= H) continue;
            unsigned lo = sur_word_f(src, gr, w - 1);
            unsigned mi = sur_word_f(src, gr, w);
            unsigned hi = sur_word_f(src, gr, w + 1);
            unsigned long long up =
                (((unsigned long long)(mi & (0xFFFFFFFFu >> (31 - bit)))) << 32) |
                (unsigned long long)lo;
            unsigned long long dn =
                (((unsigned long long)hi) << (32 - bit)) |
                (unsigned long long)(mi >> bit);
            int dl = up ? (bit + 32) - (63 - __clzll(up)) : MISS;
            int drr = dn ? (__ffsll((long long)dn) - 1)   : MISS;
            int dc = min(dl, drr);
            if (dc <= 32) {
                best = fminf(best, (float)(dr2 + dc * dc));
            } else if ((float)(dr2 + 1024) < best) {
                int dfl = MISS, dfr = MISS;
                for (int ww = w - 2; ww >= 0; --ww) {
                    unsigned x = sur_word_f(src, gr, ww);
                    if (x) { dfl = (w - ww) * 32 + bit - (31 - __clz(x)); break; }
                }
                for (int ww = w + 2; ww < WPR; ++ww) {
                    unsigned x = sur_word_f(src, gr, ww);
                    if (x) { dfr = (ww - w) * 32 - bit + (__ffs(x) - 1); break; }
                }
                int dm = min(min(dfl, dfr), dc);
                if (dm < MISS)
                    best = fminf(best, (float)(dr2 + dm * dm));
            }
        }
    }
    return sqrtf(best);
}

// ===========================================================================
// Single kernel, 128 blocks x 512 threads (1 block/SM, single wave).
// Block b handles rows 4b..4b+3:
//   loads in 3 batches of 4 rows (MLP_p1 ~ 8) with ballot/STS interleaved
//   -> bitwise erosion stage -> per-word ball-dilation counting (128 thr)
//   -> per-warp folds -> distinct-address partials -> last-block fold.
// ===========================================================================
__global__ void __launch_bounds__(512) k_all(const float* __restrict__ pred,
                                             const float* __restrict__ gt,
                                             float* __restrict__ out) {
    __shared__ unsigned sraw[2][12][WPR];   // raw rows gb-4..gb+7
    __shared__ unsigned stg[2][10][18];     // surface rows gb-3..gb+6, padded
    __shared__ float wNum[16], wDen[16];
    __shared__ bool  isLast;

    const int c = threadIdx.x;
    const int lane = c & 31;
    const int wwarp = c >> 5;               // warp id == word index
    const int gb = blockIdx.x * 4;

    // ---- batched loads: 3 batches x 4 rows x 2 features ----
    #pragma unroll
    for (int bb = 0; bb < 3; ++bb) {
        float pv[4], gv[4];
        #pragma unroll
        for (int k = 0; k < 4; ++k) {
            int rr = bb * 4 + k;
            int gr = gb - 4 + rr;
            bool ok = (gr >= 0) && (gr < H);
            pv[k] = ok ? pred[gr * W + c] : 0.0f;
            gv[k] = ok ? gt[gr * W + c]   : 0.0f;
        }
        #pragma unroll
        for (int k = 0; k < 4; ++k) {
            int rr = bb * 4 + k;
            unsigned ba = __ballot_sync(0xFFFFFFFFu, pv[k] != 0.0f);
            unsigned bg = __ballot_sync(0xFFFFFFFFu, gv[k] != 0.0f);
            if (lane == 0) { sraw[0][rr][wwarp] = ba; sraw[1][rr][wwarp] = bg; }
        }
    }
    __syncthreads();

    // ---- bitwise erosion -> padded surface rows (10 rows x 16 words x 2) ----
    if (c < 320) {
        int f = c / 160, rest = c % 160;
        int rr = rest >> 4, ww = rest & 15;   // rr 0..9 -> surface row gb-3+rr
        int ri = rr + 1;                      // center raw row index
        unsigned cen = sraw[f][ri][ww];
        unsigned up = sraw[f][ri - 1][ww];
        unsigned dn = sraw[f][ri + 1][ww];
        unsigned lw = (ww > 0)  ? sraw[f][ri][ww - 1] : 0u;
        unsigned rw = (ww < 15) ? sraw[f][ri][ww + 1] : 0u;
        unsigned lm = (cen << 1) | (lw >> 31);
        unsigned rm = (cen >> 1) | (rw << 31);
        stg[f][rr][ww + 1] = cen & ~(up & dn & lm & rm);
    } else if (c < 360) {
        int idx = c - 320;                    // 40 pad words -> 0
        int f = idx / 20, rest = idx % 20;
        stg[f][rest >> 1][(rest & 1) ? 17 : 0] = 0u;
    }
    __syncthreads();

    // ---- per-word ball-dilation counting (2 feat x 4 rows x 16 words) ----
    float num = 0.0f;
    float den = 0.0f;

    if (c < 128) {
        const int f = c >> 6;            // dilated (source) feature
        const int local = c & 63;
        const int rloc = local >> 4;     // 0..3
        const int w = local & 15;
        const int gr = gb + rloc;

        unsigned a0c0, a0c1, a0c2, a0c3;
        unsigned a1c0 = 0, a1c1 = 0, a1c2 = 0, a1c3 = 0;
        unsigned a2c0 = 0, a2c1 = 0, a2c2 = 0;
        unsigned a3c0 = 0, a3c1 = 0;

        #pragma unroll
        for (int dr = -3; dr <= 3; ++dr) {
            const unsigned* row = &stg[f][rloc + 3 + dr][0];
            unsigned lo = row[w], mi = row[w + 1], hi = row[w + 2];
            unsigned c0 = mi;
            unsigned c1 = __funnelshift_r(mi, hi, 1) | __funnelshift_l(lo, mi, 1);
            const int adr = (dr < 0) ? -dr : dr;
            if (adr == 0) {
                a0c0 = c0; a0c1 = c1;
                a0c2 = __funnelshift_r(mi, hi, 2) | __funnelshift_l(lo, mi, 2);
                a0c3 = __funnelshift_r(mi, hi, 3) | __funnelshift_l(lo, mi, 3);
            } else if (adr == 1) {
                a1c0 |= c0; a1c1 |= c1;
                a1c2 |= __funnelshift_r(mi, hi, 2) | __funnelshift_l(lo, mi, 2);
                a1c3 |= __funnelshift_r(mi, hi, 3) | __funnelshift_l(lo, mi, 3);
            } else if (adr == 2) {
                a2c0 |= c0; a2c1 |= c1;
                a2c2 |= __funnelshift_r(mi, hi, 2) | __funnelshift_l(lo, mi, 2);
            } else {
                a3c0 |= c0; a3c1 |= c1;
            }
        }

        const unsigned tgt = stg[f ^ 1][rloc + 3][w + 1];
        den = (float)__popc(tgt);

        // incremental ball dilations: d^2 = 0,1,2,4,5,8,9,10
        unsigned D = a0c0, Dn;
        Dn = D | a0c1 | a1c0; num += 1.0f        * (float)__popc(tgt & Dn & ~D); D = Dn;
        Dn = D | a1c1;        num += 1.41421356f * (float)__popc(tgt & Dn & ~D); D = Dn;
        Dn = D | a0c2 | a2c0; num += 2.0f        * (float)__popc(tgt & Dn & ~D); D = Dn;
        Dn = D | a1c2 | a2c1; num += 2.23606798f * (float)__popc(tgt & Dn & ~D); D = Dn;
        Dn = D | a2c2;        num += 2.82842712f * (float)__popc(tgt & Dn & ~D); D = Dn;
        Dn = D | a0c3 | a3c0; num += 3.0f        * (float)__popc(tgt & Dn & ~D); D = Dn;
        Dn = D | a1c3 | a3c1; num += 3.16227766f * (float)__popc(tgt & Dn & ~D); D = Dn;

        // cold exact fallback (recomputes masks straight from float inputs)
        unsigned rem = tgt & ~D;
        while (rem) {
            int bt = __ffs(rem) - 1;
            rem &= rem - 1u;
            num += search_fb(f ? gt : pred, gr, w, bt);
        }
    }

    // ---- deterministic reduction + last-block fold ----
    #pragma unroll
    for (int off = 16; off > 0; off >>= 1) {
        num += __shfl_down_sync(0xFFFFFFFFu, num, off);
        den += __shfl_down_sync(0xFFFFFFFFu, den, off);
    }
    if (lane == 0) { wNum[wwarp] = num; wDen[wwarp] = den; }
    __syncthreads();

    if (wwarp == 0) {
        float n = (lane < 4) ? wNum[lane] : 0.0f;   // only warps 0..3 nonzero
        float d = (lane < 4) ? wDen[lane] : 0.0f;
        #pragma unroll
        for (int off = 2; off > 0; off >>= 1) {
            n += __shfl_down_sync(0xFFFFFFFFu, n, off);
            d += __shfl_down_sync(0xFFFFFFFFu, d, off);
        }
        if (lane == 0) {
            d_blkNum[blockIdx.x] = n;
            d_blkDen[blockIdx.x] = d;
            __threadfence();
            unsigned old = atomicInc(&d_cnt, GRID - 1);  // wraps -> self-reset
            isLast = (old == GRID - 1);
        }
    }
    __syncthreads();

    if (isLast) {
        float n = (c < GRID) ? d_blkNum[c] : 0.0f;
        float d = (c < GRID) ? d_blkDen[c] : 0.0f;
        #pragma unroll
        for (int off = 16; off > 0; off >>= 1) {
            n += __shfl_down_sync(0xFFFFFFFFu, n, off);
            d += __shfl_down_sync(0xFFFFFFFFu, d, off);
        }
        if (lane == 0) { wNum[wwarp] = n; wDen[wwarp] = d; }
        __syncthreads();
        if (wwarp == 0) {
            float nn = (lane < 4) ? wNum[lane] : 0.0f;  // warps 0..3 of first 128
            float dd = (lane < 4) ? wDen[lane] : 0.0f;
            #pragma unroll
            for (int off = 2; off > 0; off >>= 1) {
                nn += __shfl_down_sync(0xFFFFFFFFu, nn, off);
                dd += __shfl_down_sync(0xFFFFFFFFu, dd, off);
            }
            if (lane == 0) out[0] = nn / dd;
        }
    }
}

extern "C" void kernel_launch(void* const* d_in, const int* in_sizes, int n_in,
                              void* d_out, int out_size) {
    const float* pred = (const float*)d_in[0];
    const float* gt   = (const float*)d_in[1];
    float* out = (float*)d_out;

    k_all<<<GRID, 512>>>(pred, gt, out);
}